// round 6
// baseline (speedup 1.0000x reference)
#include <cuda_runtime.h>
#include <cuda_fp16.h>
#include <math.h>

#define NMAX 100000
#define EMAX 1600000
#define CIN  64

// ---------------- device scratch (no allocation allowed) ----------------
__device__ int   g_is64;
__device__ int   g_src[EMAX];
__device__ int   g_dstE[EMAX];
__device__ int   g_esrc[EMAX];          // CSR: src ids sorted by dst
__device__ int   g_cnt[NMAX];
__device__ int   g_scan[NMAX];
__device__ int   g_bsum[512];
__device__ int   g_boff[512];
__device__ int   g_rowstart[NMAX + 1];
__device__ int   g_cur[NMAX];
__device__ float g_inv[NMAX];
__device__ __align__(256) __half g_ylh[(size_t)NMAX * 64];   // fp16 gather payload
__device__ __align__(256) float  g_yr[(size_t)NMAX * 64];
__device__ __align__(256) float  g_h0[(size_t)NMAX * 64];
__device__ __align__(256) float  g_h1[(size_t)NMAX * 64];
__device__ float g_stats0[128];         // layer0: [sum(64) | sumsq(64)]
__device__ float g_stats1[128];         // layer1

// ---------------- packed f32x2 helpers ----------------
__device__ __forceinline__ unsigned long long pk2(float lo, float hi) {
    unsigned long long r;
    asm("mov.b64 %0, {%1, %2};" : "=l"(r) : "f"(lo), "f"(hi));
    return r;
}
__device__ __forceinline__ void upk2(unsigned long long v, float& lo, float& hi) {
    asm("mov.b64 {%0, %1}, %2;" : "=f"(lo), "=f"(hi) : "l"(v));
}
__device__ __forceinline__ void fma2(unsigned long long& d,
                                     unsigned long long a, unsigned long long b) {
    asm("fma.rn.f32x2 %0, %1, %2, %3;" : "=l"(d) : "l"(a), "l"(b), "l"(d));
}

// ---------------- pre: zero cnt + zero stats + dtype detect ----------------
__global__ void k_pre(const unsigned int* __restrict__ w, int N) {
    int i = blockIdx.x * 256 + threadIdx.x;
    if (i < N) g_cnt[i] = 0;
    if (blockIdx.x == 0 && threadIdx.x < 128) {
        g_stats0[threadIdx.x] = 0.0f;
        g_stats1[threadIdx.x] = 0.0f;
    }
    if (blockIdx.x == 1) {
        int ok = 1;
#pragma unroll
        for (int r = 0; r < 8; r++) {
            int q = threadIdx.x * 8 + r;       // 2048 odd words checked
            ok &= (w[2 * q + 1] == 0u);
        }
        int all = __syncthreads_and(ok);
        if (threadIdx.x == 0) g_is64 = all ? 1 : 0;
    }
}

__global__ void k_decode(const void* __restrict__ ei, int E) {
    int i = blockIdx.x * blockDim.x + threadIdx.x;
    if (i >= E) return;
    int s, d;
    if (g_is64) {
        const long long* p = (const long long*)ei;
        s = (int)p[i];
        d = (int)p[E + i];
    } else {
        const int* p = (const int*)ei;
        s = p[i];
        d = p[E + i];
    }
    g_src[i] = s;
    g_dstE[i] = d;
    atomicAdd(&g_cnt[d], 1);
}

__global__ void k_scan1(int N) {
    __shared__ int sh[256];
    int i = blockIdx.x * 256 + threadIdx.x;
    int v = (i < N) ? g_cnt[i] : 0;
    sh[threadIdx.x] = v;
    __syncthreads();
    for (int off = 1; off < 256; off <<= 1) {
        int t = (threadIdx.x >= off) ? sh[threadIdx.x - off] : 0;
        __syncthreads();
        sh[threadIdx.x] += t;
        __syncthreads();
    }
    if (i < N) g_scan[i] = sh[threadIdx.x] - v;
    if (threadIdx.x == 255) g_bsum[blockIdx.x] = sh[255];
}

__global__ void k_scan2(int NB) {
    __shared__ int sh[512];
    int i = threadIdx.x;
    int v = (i < NB) ? g_bsum[i] : 0;
    sh[i] = v;
    __syncthreads();
    for (int off = 1; off < 512; off <<= 1) {
        int t = (i >= off) ? sh[i - off] : 0;
        __syncthreads();
        sh[i] += t;
        __syncthreads();
    }
    g_boff[i] = sh[i] - v;
}

__global__ void k_scan3(int N, int E) {
    int i = blockIdx.x * blockDim.x + threadIdx.x;
    if (i < N) {
        int rs = g_scan[i] + g_boff[i >> 8];
        g_rowstart[i] = rs;
        g_cur[i] = rs;
        g_inv[i] = 1.0f / fmaxf((float)g_cnt[i], 1.0f);
    }
    if (i == N) g_rowstart[N] = E;
}

__global__ void k_fill(int E) {
    int i = blockIdx.x * blockDim.x + threadIdx.x;
    if (i >= E) return;
    int d = g_dstE[i];
    int pos = atomicAdd(&g_cur[d], 1);
    g_esrc[pos] = g_src[i];
}

// ---------------- linear: ylh = half(f(x)@Wl), yr = f(x)@Wr + b ----------------
// f = relu(bn(.)) when AFFINE (affine computed in-block from raw stats), else id.
template <int COUT, bool AFFINE>
__global__ void __launch_bounds__((COUT / 4) * 16)
k_lin(const float* __restrict__ x,
      const float* __restrict__ stats,
      const float* __restrict__ gamma,
      const float* __restrict__ beta,
      const float* __restrict__ Wl,
      const float* __restrict__ Wr,
      const float* __restrict__ bias,
      __half* __restrict__ ylh,
      float* __restrict__ yr,
      int N, float invN) {
    constexpr int CQ = COUT / 4;
    constexpr int NT = 64;
    constexpr int THREADS = CQ * 16;
    constexpr int RS = CIN + 4;
    constexpr int HALF = COUT / 2;

    extern __shared__ float smem[];
    float* sX  = smem;                  // NT*RS
    float* sWl = sX + NT * RS;          // CIN*COUT
    float* sWr = sWl + CIN * COUT;      // CIN*COUT
    __shared__ float sAff[128];

    int tid = threadIdx.x;
    if (AFFINE && tid < 64) {
        float mu  = stats[tid] * invN;
        float var = stats[64 + tid] * invN - mu * mu;
        float a = gamma[tid] * rsqrtf(var + 1e-5f);
        sAff[tid] = a;
        sAff[64 + tid] = beta[tid] - mu * a;
    }
    for (int i = tid; i < CIN * COUT; i += THREADS) {
        sWl[i] = Wl[i];
        sWr[i] = Wr[i];
    }
    if (AFFINE) __syncthreads();        // sAff ready before staging

    int tile = blockIdx.x * NT;
    for (int q = tid; q < NT * (CIN / 4); q += THREADS) {
        int row = q / (CIN / 4);
        int c4  = (q % (CIN / 4)) * 4;
        int n = tile + row;
        float4 xv = make_float4(0.f, 0.f, 0.f, 0.f);
        if (n < N) {
            xv = *reinterpret_cast<const float4*>(x + (size_t)n * CIN + c4);
            if (AFFINE) {
                xv.x = fmaxf(fmaf(xv.x, sAff[c4 + 0], sAff[64 + c4 + 0]), 0.f);
                xv.y = fmaxf(fmaf(xv.y, sAff[c4 + 1], sAff[64 + c4 + 1]), 0.f);
                xv.z = fmaxf(fmaf(xv.z, sAff[c4 + 2], sAff[64 + c4 + 2]), 0.f);
                xv.w = fmaxf(fmaf(xv.w, sAff[c4 + 3], sAff[64 + c4 + 3]), 0.f);
            }
        }
        *reinterpret_cast<float4*>(sX + row * RS + c4) = xv;
    }
    __syncthreads();

    int cog = tid % CQ;
    int nb  = (tid / CQ) * 4;
    int ch0 = 2 * cog;

    unsigned long long accl[4][2], accr[4][2];
#pragma unroll
    for (int j = 0; j < 2; j++) {
        float2 b = *reinterpret_cast<const float2*>(bias + ch0 + j * HALF);
        unsigned long long bp = pk2(b.x, b.y);
#pragma unroll
        for (int i = 0; i < 4; i++) { accl[i][j] = pk2(0.f, 0.f); accr[i][j] = bp; }
    }

#pragma unroll 4
    for (int k = 0; k < CIN; k++) {
        unsigned long long wl2[2], wr2[2], xp[4];
#pragma unroll
        for (int j = 0; j < 2; j++) {
            float2 wl = *reinterpret_cast<const float2*>(sWl + k * COUT + ch0 + j * HALF);
            float2 wr = *reinterpret_cast<const float2*>(sWr + k * COUT + ch0 + j * HALF);
            wl2[j] = pk2(wl.x, wl.y);
            wr2[j] = pk2(wr.x, wr.y);
        }
#pragma unroll
        for (int i = 0; i < 4; i++) {
            float xv = sX[(nb + i) * RS + k];
            xp[i] = pk2(xv, xv);
        }
#pragma unroll
        for (int i = 0; i < 4; i++)
#pragma unroll
            for (int j = 0; j < 2; j++) {
                fma2(accl[i][j], xp[i], wl2[j]);
                fma2(accr[i][j], xp[i], wr2[j]);
            }
    }

#pragma unroll
    for (int i = 0; i < 4; i++) {
        int n = tile + nb + i;
        if (n < N) {
#pragma unroll
            for (int j = 0; j < 2; j++) {
                float lo, hi;
                upk2(accl[i][j], lo, hi);
                *reinterpret_cast<__half2*>(ylh + (size_t)n * COUT + ch0 + j * HALF) =
                    __floats2half2_rn(lo, hi);
                upk2(accr[i][j], lo, hi);
                *reinterpret_cast<float2*>(yr + (size_t)n * COUT + ch0 + j * HALF) =
                    make_float2(lo, hi);
            }
        }
    }
}

// ---------------- CSR gather reduce: out = invdeg * sum ylh[src] + yr ----------------
// 8-lane octet per node; lane l loads index base+l, shfl-broadcasts, 8 gathers
// in flight per iteration. Lane l owns channels [8l, 8l+8) (idle if >= COUT).
template <int COUT, bool STATS>
__global__ void __launch_bounds__(256)
k_agg(const __half* __restrict__ ylh,
      const float* __restrict__ yrr,
      float* __restrict__ out,
      float* __restrict__ stats,
      int N) {
    __shared__ float sSum[64];
    __shared__ float sSq[64];
    int tid = threadIdx.x;
    if (STATS) {
        if (tid < 64) { sSum[tid] = 0.0f; sSq[tid] = 0.0f; }
        __syncthreads();
    }

    int t = blockIdx.x * 256 + tid;
    int n = t >> 3;
    int l = t & 7;
    int c = l * 8;
    bool dataLane = (c < COUT);
    bool active = (n < N);
    unsigned omask = 0xFFu << ((tid & 31) & ~7);

    float r[8];
    if (active) {
        int beg = g_rowstart[n];
        int end = g_rowstart[n + 1];
        float a[8];
#pragma unroll
        for (int k = 0; k < 8; k++) a[k] = 0.0f;

        for (int base = beg; base < end; base += 8) {
            int t8 = base + l;
            int myIdx = (t8 < end) ? g_esrc[t8] : -1;
#pragma unroll
            for (int j = 0; j < 8; j++) {
                int s = __shfl_sync(omask, myIdx, j, 8);
                if (s >= 0 && dataLane) {
                    uint4 v = *reinterpret_cast<const uint4*>(ylh + (size_t)s * COUT + c);
                    float2 f0 = __half22float2(*reinterpret_cast<__half2*>(&v.x));
                    float2 f1 = __half22float2(*reinterpret_cast<__half2*>(&v.y));
                    float2 f2 = __half22float2(*reinterpret_cast<__half2*>(&v.z));
                    float2 f3 = __half22float2(*reinterpret_cast<__half2*>(&v.w));
                    a[0] += f0.x; a[1] += f0.y;
                    a[2] += f1.x; a[3] += f1.y;
                    a[4] += f2.x; a[5] += f2.y;
                    a[6] += f3.x; a[7] += f3.y;
                }
            }
        }

        if (dataLane) {
            float inv = g_inv[n];
            float4 b0 = *reinterpret_cast<const float4*>(yrr + (size_t)n * COUT + c);
            float4 b1 = *reinterpret_cast<const float4*>(yrr + (size_t)n * COUT + c + 4);
            r[0] = fmaf(a[0], inv, b0.x);
            r[1] = fmaf(a[1], inv, b0.y);
            r[2] = fmaf(a[2], inv, b0.z);
            r[3] = fmaf(a[3], inv, b0.w);
            r[4] = fmaf(a[4], inv, b1.x);
            r[5] = fmaf(a[5], inv, b1.y);
            r[6] = fmaf(a[6], inv, b1.z);
            r[7] = fmaf(a[7], inv, b1.w);
            *reinterpret_cast<float4*>(out + (size_t)n * COUT + c) =
                make_float4(r[0], r[1], r[2], r[3]);
            *reinterpret_cast<float4*>(out + (size_t)n * COUT + c + 4) =
                make_float4(r[4], r[5], r[6], r[7]);
        }
    }

    if (STATS) {
        if (active && dataLane) {
#pragma unroll
            for (int k = 0; k < 8; k++) {
                atomicAdd(&sSum[c + k], r[k]);
                atomicAdd(&sSq[c + k],  r[k] * r[k]);
            }
        }
        __syncthreads();
        if (tid < 64) {
            atomicAdd(&stats[tid],      sSum[tid]);
            atomicAdd(&stats[64 + tid], sSq[tid]);
        }
    }
}

// ---------------- launch ----------------
extern "C" void kernel_launch(void* const* d_in, const int* in_sizes, int n_in,
                              void* d_out, int out_size) {
    const float* x   = (const float*)d_in[0];
    const void*  ei  = d_in[1];
    const float* Wl0 = (const float*)d_in[2];
    const float* Wr0 = (const float*)d_in[3];
    const float* b0  = (const float*)d_in[4];
    const float* Wl1 = (const float*)d_in[5];
    const float* Wr1 = (const float*)d_in[6];
    const float* b1  = (const float*)d_in[7];
    const float* Wl2 = (const float*)d_in[8];
    const float* Wr2 = (const float*)d_in[9];
    const float* b2  = (const float*)d_in[10];
    const float* g0  = (const float*)d_in[11];
    const float* be0 = (const float*)d_in[12];
    const float* g1  = (const float*)d_in[13];
    const float* be1 = (const float*)d_in[14];
    float* out = (float*)d_out;

    int N = in_sizes[0] / 64;
    int E = in_sizes[1] / 2;
    float invN = 1.0f / (float)N;

    __half* ylhp;
    float *yrp, *h0p, *h1p, *st0p, *st1p;
    cudaGetSymbolAddress((void**)&ylhp, g_ylh);
    cudaGetSymbolAddress((void**)&yrp, g_yr);
    cudaGetSymbolAddress((void**)&h0p, g_h0);
    cudaGetSymbolAddress((void**)&h1p, g_h1);
    cudaGetSymbolAddress((void**)&st0p, g_stats0);
    cudaGetSymbolAddress((void**)&st1p, g_stats1);

    const int smem64 = (64 * (CIN + 4) + 2 * CIN * 64) * 4;
    const int smem40 = (64 * (CIN + 4) + 2 * CIN * 40) * 4;
    cudaFuncSetAttribute(k_lin<64, false>,
                         cudaFuncAttributeMaxDynamicSharedMemorySize, smem64);
    cudaFuncSetAttribute(k_lin<64, true>,
                         cudaFuncAttributeMaxDynamicSharedMemorySize, smem64);
    cudaFuncSetAttribute(k_lin<40, true>,
                         cudaFuncAttributeMaxDynamicSharedMemorySize, smem40);

    const int nodeBlocks  = (N + 255) / 256;
    const int nodeBlocks1 = (N + 256) / 256;
    const int edgeBlocks  = (E + 255) / 256;
    const int NB          = (N + 255) / 256;
    const int aggBlocks   = (N * 8 + 255) / 256;
    const int mmGrid      = (N + 63) / 64;

    // 0: pre (zero cnt+stats, dtype detect)
    k_pre<<<nodeBlocks, 256>>>((const unsigned int*)ei, N);
    // 1: decode + degree histogram
    k_decode<<<edgeBlocks, 256>>>(ei, E);
    // 2: scan level 1
    k_scan1<<<NB, 256>>>(N);
    // 3: layer-0 linear (CSR-independent; placed here so ncu profiles it)
    k_lin<64, false><<<mmGrid, 256, smem64>>>(x, nullptr, nullptr, nullptr,
                                              Wl0, Wr0, b0, ylhp, yrp, N, invN);
    // 4-6: finish CSR build
    k_scan2<<<1, 512>>>(NB);
    k_scan3<<<nodeBlocks1, 256>>>(N, E);
    k_fill<<<edgeBlocks, 256>>>(E);
    // 7: layer-0 aggregate (+ stats0)
    k_agg<64, true><<<aggBlocks, 256>>>(ylhp, yrp, h0p, st0p, N);
    // 8: layer-1 linear (bn0 affine computed in-block from stats0)
    k_lin<64, true><<<mmGrid, 256, smem64>>>(h0p, st0p, g0, be0,
                                             Wl1, Wr1, b1, ylhp, yrp, N, invN);
    // 9: layer-1 aggregate (+ stats1)
    k_agg<64, true><<<aggBlocks, 256>>>(ylhp, yrp, h1p, st1p, N);
    // 10: layer-2 linear (bn1 affine from stats1)
    k_lin<40, true><<<mmGrid, 160, smem40>>>(h1p, st1p, g1, be1,
                                             Wl2, Wr2, b2, ylhp, yrp, N, invN);
    // 11: layer-2 aggregate -> final output
    k_agg<40, false><<<aggBlocks, 256>>>(ylhp, yrp, out, nullptr, N);
}

// round 7
// speedup vs baseline: 1.0847x; 1.0847x over previous
#include <cuda_runtime.h>
#include <cuda_fp16.h>
#include <math.h>

#define NMAX 100000
#define EMAX 1600000
#define CIN  64

// ---------------- device scratch (no allocation allowed) ----------------
__device__ int   g_is64;
__device__ int   g_src[EMAX];
__device__ int   g_dstE[EMAX];
__device__ int   g_esrc[EMAX];          // CSR: src ids sorted by dst
__device__ int   g_cnt[NMAX];
__device__ int   g_scan[NMAX];
__device__ int   g_bsum[512];
__device__ int   g_boff[512];
__device__ int   g_rowstart[NMAX + 1];
__device__ int   g_cur[NMAX];
__device__ float g_inv[NMAX];
__device__ __align__(256) __half g_ylh[(size_t)NMAX * 64];   // fp16 gather payload
__device__ __align__(256) float  g_yr[(size_t)NMAX * 64];
__device__ __align__(256) float  g_h0[(size_t)NMAX * 64];
__device__ __align__(256) float  g_h1[(size_t)NMAX * 64];
__device__ float g_stats0[128];         // layer0: [sum(64) | sumsq(64)]
__device__ float g_stats1[128];         // layer1

// ---------------- packed f32x2 helpers ----------------
__device__ __forceinline__ unsigned long long pk2(float lo, float hi) {
    unsigned long long r;
    asm("mov.b64 %0, {%1, %2};" : "=l"(r) : "f"(lo), "f"(hi));
    return r;
}
__device__ __forceinline__ void upk2(unsigned long long v, float& lo, float& hi) {
    asm("mov.b64 {%0, %1}, %2;" : "=f"(lo), "=f"(hi) : "l"(v));
}
__device__ __forceinline__ void fma2(unsigned long long& d,
                                     unsigned long long a, unsigned long long b) {
    asm("fma.rn.f32x2 %0, %1, %2, %3;" : "=l"(d) : "l"(a), "l"(b), "l"(d));
}

// ---------------- pre: zero cnt + zero stats + dtype detect ----------------
__global__ void k_pre(const unsigned int* __restrict__ w, int N) {
    int i = blockIdx.x * 256 + threadIdx.x;
    if (i < N) g_cnt[i] = 0;
    if (blockIdx.x == 0 && threadIdx.x < 128) {
        g_stats0[threadIdx.x] = 0.0f;
        g_stats1[threadIdx.x] = 0.0f;
    }
    if (blockIdx.x == 1) {
        int ok = 1;
#pragma unroll
        for (int r = 0; r < 8; r++) {
            int q = threadIdx.x * 8 + r;       // 2048 odd words checked
            ok &= (w[2 * q + 1] == 0u);
        }
        int all = __syncthreads_and(ok);
        if (threadIdx.x == 0) g_is64 = all ? 1 : 0;
    }
}

__global__ void k_decode(const void* __restrict__ ei, int E) {
    int i = blockIdx.x * blockDim.x + threadIdx.x;
    if (i >= E) return;
    int s, d;
    if (g_is64) {
        const long long* p = (const long long*)ei;
        s = (int)p[i];
        d = (int)p[E + i];
    } else {
        const int* p = (const int*)ei;
        s = p[i];
        d = p[E + i];
    }
    g_src[i] = s;
    g_dstE[i] = d;
    atomicAdd(&g_cnt[d], 1);
}

__global__ void k_scan1(int N) {
    __shared__ int sh[256];
    int i = blockIdx.x * 256 + threadIdx.x;
    int v = (i < N) ? g_cnt[i] : 0;
    sh[threadIdx.x] = v;
    __syncthreads();
    for (int off = 1; off < 256; off <<= 1) {
        int t = (threadIdx.x >= off) ? sh[threadIdx.x - off] : 0;
        __syncthreads();
        sh[threadIdx.x] += t;
        __syncthreads();
    }
    if (i < N) g_scan[i] = sh[threadIdx.x] - v;
    if (threadIdx.x == 255) g_bsum[blockIdx.x] = sh[255];
}

__global__ void k_scan2(int NB) {
    __shared__ int sh[512];
    int i = threadIdx.x;
    int v = (i < NB) ? g_bsum[i] : 0;
    sh[i] = v;
    __syncthreads();
    for (int off = 1; off < 512; off <<= 1) {
        int t = (i >= off) ? sh[i - off] : 0;
        __syncthreads();
        sh[i] += t;
        __syncthreads();
    }
    g_boff[i] = sh[i] - v;
}

__global__ void k_scan3(int N, int E) {
    int i = blockIdx.x * blockDim.x + threadIdx.x;
    if (i < N) {
        int rs = g_scan[i] + g_boff[i >> 8];
        g_rowstart[i] = rs;
        g_cur[i] = rs;
        g_inv[i] = 1.0f / fmaxf((float)g_cnt[i], 1.0f);
    }
    if (i == N) g_rowstart[N] = E;
}

__global__ void k_fill(int E) {
    int i = blockIdx.x * blockDim.x + threadIdx.x;
    if (i >= E) return;
    int d = g_dstE[i];
    int pos = atomicAdd(&g_cur[d], 1);
    g_esrc[pos] = g_src[i];
}

// ---------------- linear: ylh = half(f(x)@Wl), yr = f(x)@Wr + b ----------------
// f = relu(bn(.)) when AFFINE (affine computed in-block from raw stats), else id.
// Combined weight matrix W = [Wl | Wr] of width 2*COUT staged in smem.
// 8 nodes x 2 channel-pairs per thread; x vectorized float4 over k.
template <int COUT, bool AFFINE>
__global__ void __launch_bounds__((COUT / 2) * 8)
k_lin(const float* __restrict__ x,
      const float* __restrict__ stats,
      const float* __restrict__ gamma,
      const float* __restrict__ beta,
      const float* __restrict__ Wl,
      const float* __restrict__ Wr,
      const float* __restrict__ bias,
      __half* __restrict__ ylh,
      float* __restrict__ yr,
      int N, float invN) {
    constexpr int W  = 2 * COUT;        // 128 or 80
    constexpr int CQ = W / 4;           // 32 or 20 channel-pair groups
    constexpr int NT = 64;              // node tile
    constexpr int THREADS = CQ * 8;     // 256 or 160
    constexpr int RS = CIN + 4;         // 68, multiple of 4

    extern __shared__ float smem[];
    float* sX = smem;                   // NT*RS
    float* sW = sX + NT * RS;           // CIN*W
    __shared__ float sAff[128];

    int tid = threadIdx.x;
    if (AFFINE && tid < 64) {
        float mu  = stats[tid] * invN;
        float var = stats[64 + tid] * invN - mu * mu;
        float a = gamma[tid] * rsqrtf(var + 1e-5f);
        sAff[tid] = a;
        sAff[64 + tid] = beta[tid] - mu * a;
    }
    // stage combined weights [k][0:COUT)=Wl row k, [COUT:W)=Wr row k
    for (int i = tid; i < CIN * W; i += THREADS) {
        int k = i / W;
        int c = i % W;
        sW[i] = (c < COUT) ? Wl[k * COUT + c] : Wr[k * COUT + (c - COUT)];
    }
    if (AFFINE) __syncthreads();

    int tile = blockIdx.x * NT;
    for (int q = tid; q < NT * (CIN / 4); q += THREADS) {
        int row = q / (CIN / 4);
        int c4  = (q % (CIN / 4)) * 4;
        int n = tile + row;
        float4 xv = make_float4(0.f, 0.f, 0.f, 0.f);
        if (n < N) {
            xv = *reinterpret_cast<const float4*>(x + (size_t)n * CIN + c4);
            if (AFFINE) {
                xv.x = fmaxf(fmaf(xv.x, sAff[c4 + 0], sAff[64 + c4 + 0]), 0.f);
                xv.y = fmaxf(fmaf(xv.y, sAff[c4 + 1], sAff[64 + c4 + 1]), 0.f);
                xv.z = fmaxf(fmaf(xv.z, sAff[c4 + 2], sAff[64 + c4 + 2]), 0.f);
                xv.w = fmaxf(fmaf(xv.w, sAff[c4 + 3], sAff[64 + c4 + 3]), 0.f);
            }
        }
        *reinterpret_cast<float4*>(sX + row * RS + c4) = xv;
    }
    __syncthreads();

    int cg  = tid % CQ;                 // channel-pair group
    int nb  = (tid / CQ) * 8;           // node base (8 nodes per thread)
    int ch0 = 2 * cg;                   // logical output channel pair {ch0, ch0+1}

    unsigned long long acc0[8], acc1[8];    // Wl-product | Wr-product
    {
        float2 b = *reinterpret_cast<const float2*>(bias + ch0);
        unsigned long long bp = pk2(b.x, b.y);
        unsigned long long zp = pk2(0.f, 0.f);
#pragma unroll
        for (int i = 0; i < 8; i++) { acc0[i] = zp; acc1[i] = bp; }
    }

    for (int k4 = 0; k4 < CIN; k4 += 4) {
        float4 xv[8];
#pragma unroll
        for (int i = 0; i < 8; i++)
            xv[i] = *reinterpret_cast<const float4*>(sX + (nb + i) * RS + k4);
#pragma unroll
        for (int kk = 0; kk < 4; kk++) {
            float2 w0 = *reinterpret_cast<const float2*>(sW + (k4 + kk) * W + ch0);
            float2 w1 = *reinterpret_cast<const float2*>(sW + (k4 + kk) * W + ch0 + COUT);
            unsigned long long w0p = pk2(w0.x, w0.y);
            unsigned long long w1p = pk2(w1.x, w1.y);
#pragma unroll
            for (int i = 0; i < 8; i++) {
                float xs = (kk == 0) ? xv[i].x : (kk == 1) ? xv[i].y
                         : (kk == 2) ? xv[i].z : xv[i].w;
                unsigned long long xp = pk2(xs, xs);
                fma2(acc0[i], xp, w0p);
                fma2(acc1[i], xp, w1p);
            }
        }
    }

#pragma unroll
    for (int i = 0; i < 8; i++) {
        int n = tile + nb + i;
        if (n < N) {
            float lo, hi;
            upk2(acc0[i], lo, hi);
            *reinterpret_cast<__half2*>(ylh + (size_t)n * COUT + ch0) =
                __floats2half2_rn(lo, hi);
            upk2(acc1[i], lo, hi);
            *reinterpret_cast<float2*>(yr + (size_t)n * COUT + ch0) =
                make_float2(lo, hi);
        }
    }
}

// ---------------- CSR gather reduce: out = invdeg * sum ylh[src] + yr ----------------
// CH = COUT/8 threads per node, each owns one 16B chunk (8 fp16 channels).
template <int COUT, bool STATS, int BLOCK>
__global__ void __launch_bounds__(BLOCK)
k_agg(const __half* __restrict__ ylh,
      const float* __restrict__ yrr,
      float* __restrict__ out,
      float* __restrict__ stats,
      int N) {
    constexpr int CH = COUT / 8;

    __shared__ float sSum[64];
    __shared__ float sSq[64];
    int tid = threadIdx.x;
    if (STATS) {
        if (tid < 64) { sSum[tid] = 0.0f; sSq[tid] = 0.0f; }
        __syncthreads();
    }

    int t = blockIdx.x * BLOCK + tid;
    int n = t / CH;
    int c = (t % CH) * 8;
    bool active = (n < N);

    float r[8];
    if (active) {
        int beg = g_rowstart[n];
        int end = g_rowstart[n + 1];
        float2 a0 = make_float2(0.f, 0.f), a1 = a0, a2 = a0, a3 = a0;
#pragma unroll 2
        for (int j = beg; j < end; j++) {
            int s = __ldg(&g_esrc[j]);
            uint4 v = *reinterpret_cast<const uint4*>(ylh + (size_t)s * COUT + c);
            float2 f0 = __half22float2(*reinterpret_cast<__half2*>(&v.x));
            float2 f1 = __half22float2(*reinterpret_cast<__half2*>(&v.y));
            float2 f2 = __half22float2(*reinterpret_cast<__half2*>(&v.z));
            float2 f3 = __half22float2(*reinterpret_cast<__half2*>(&v.w));
            a0.x += f0.x; a0.y += f0.y;
            a1.x += f1.x; a1.y += f1.y;
            a2.x += f2.x; a2.y += f2.y;
            a3.x += f3.x; a3.y += f3.y;
        }
        float inv = g_inv[n];
        float4 b0 = *reinterpret_cast<const float4*>(yrr + (size_t)n * COUT + c);
        float4 b1 = *reinterpret_cast<const float4*>(yrr + (size_t)n * COUT + c + 4);
        r[0] = fmaf(a0.x, inv, b0.x);
        r[1] = fmaf(a0.y, inv, b0.y);
        r[2] = fmaf(a1.x, inv, b0.z);
        r[3] = fmaf(a1.y, inv, b0.w);
        r[4] = fmaf(a2.x, inv, b1.x);
        r[5] = fmaf(a2.y, inv, b1.y);
        r[6] = fmaf(a3.x, inv, b1.z);
        r[7] = fmaf(a3.y, inv, b1.w);
        *reinterpret_cast<float4*>(out + (size_t)n * COUT + c) =
            make_float4(r[0], r[1], r[2], r[3]);
        *reinterpret_cast<float4*>(out + (size_t)n * COUT + c + 4) =
            make_float4(r[4], r[5], r[6], r[7]);
    }

    if (STATS) {
        if (active) {
#pragma unroll
            for (int k = 0; k < 8; k++) {
                atomicAdd(&sSum[c + k], r[k]);
                atomicAdd(&sSq[c + k],  r[k] * r[k]);
            }
        }
        __syncthreads();
        if (tid < 64) {
            atomicAdd(&stats[tid],      sSum[tid]);
            atomicAdd(&stats[64 + tid], sSq[tid]);
        }
    }
}

// ---------------- launch ----------------
extern "C" void kernel_launch(void* const* d_in, const int* in_sizes, int n_in,
                              void* d_out, int out_size) {
    const float* x   = (const float*)d_in[0];
    const void*  ei  = d_in[1];
    const float* Wl0 = (const float*)d_in[2];
    const float* Wr0 = (const float*)d_in[3];
    const float* b0  = (const float*)d_in[4];
    const float* Wl1 = (const float*)d_in[5];
    const float* Wr1 = (const float*)d_in[6];
    const float* b1  = (const float*)d_in[7];
    const float* Wl2 = (const float*)d_in[8];
    const float* Wr2 = (const float*)d_in[9];
    const float* b2  = (const float*)d_in[10];
    const float* g0  = (const float*)d_in[11];
    const float* be0 = (const float*)d_in[12];
    const float* g1  = (const float*)d_in[13];
    const float* be1 = (const float*)d_in[14];
    float* out = (float*)d_out;

    int N = in_sizes[0] / 64;
    int E = in_sizes[1] / 2;
    float invN = 1.0f / (float)N;

    __half* ylhp;
    float *yrp, *h0p, *h1p, *st0p, *st1p;
    cudaGetSymbolAddress((void**)&ylhp, g_ylh);
    cudaGetSymbolAddress((void**)&yrp, g_yr);
    cudaGetSymbolAddress((void**)&h0p, g_h0);
    cudaGetSymbolAddress((void**)&h1p, g_h1);
    cudaGetSymbolAddress((void**)&st0p, g_stats0);
    cudaGetSymbolAddress((void**)&st1p, g_stats1);

    const int smem64 = (64 * (CIN + 4) + CIN * 128) * 4;
    const int smem40 = (64 * (CIN + 4) + CIN * 80) * 4;
    cudaFuncSetAttribute(k_lin<64, false>,
                         cudaFuncAttributeMaxDynamicSharedMemorySize, smem64);
    cudaFuncSetAttribute(k_lin<64, true>,
                         cudaFuncAttributeMaxDynamicSharedMemorySize, smem64);
    cudaFuncSetAttribute(k_lin<40, true>,
                         cudaFuncAttributeMaxDynamicSharedMemorySize, smem40);

    const int nodeBlocks  = (N + 255) / 256;
    const int nodeBlocks1 = (N + 256) / 256;
    const int edgeBlocks  = (E + 255) / 256;
    const int NB          = (N + 255) / 256;
    const int agg64Blocks = (N * 8 + 255) / 256;
    const int agg40Blocks = (N * 5 + 319) / 320;
    const int mmGrid      = (N + 63) / 64;

    // 0: pre (zero cnt+stats, dtype detect)
    k_pre<<<nodeBlocks, 256>>>((const unsigned int*)ei, N);
    // 1: decode + degree histogram
    k_decode<<<edgeBlocks, 256>>>(ei, E);
    // 2: scan level 1
    k_scan1<<<NB, 256>>>(N);
    // 3: layer-0 linear (CSR-independent; placed here so ncu profiles it)
    k_lin<64, false><<<mmGrid, 256, smem64>>>(x, nullptr, nullptr, nullptr,
                                              Wl0, Wr0, b0, ylhp, yrp, N, invN);
    // 4-6: finish CSR build
    k_scan2<<<1, 512>>>(NB);
    k_scan3<<<nodeBlocks1, 256>>>(N, E);
    k_fill<<<edgeBlocks, 256>>>(E);
    // 7: layer-0 aggregate (+ stats0)
    k_agg<64, true, 256><<<agg64Blocks, 256>>>(ylhp, yrp, h0p, st0p, N);
    // 8: layer-1 linear (bn0 affine computed in-block from stats0)
    k_lin<64, true><<<mmGrid, 256, smem64>>>(h0p, st0p, g0, be0,
                                             Wl1, Wr1, b1, ylhp, yrp, N, invN);
    // 9: layer-1 aggregate (+ stats1)
    k_agg<64, true, 256><<<agg64Blocks, 256>>>(ylhp, yrp, h1p, st1p, N);
    // 10: layer-2 linear (bn1 affine from stats1)
    k_lin<40, true><<<mmGrid, 160, smem40>>>(h1p, st1p, g1, be1,
                                             Wl2, Wr2, b2, ylhp, yrp, N, invN);
    // 11: layer-2 aggregate -> final output
    k_agg<40, false, 320><<<agg40Blocks, 320>>>(ylhp, yrp, out, nullptr, N);
}

// round 8
// speedup vs baseline: 1.6134x; 1.4874x over previous
#include <cuda_runtime.h>
#include <cuda_fp16.h>
#include <math.h>

#define NMAX 100000
#define EMAX 1600000
#define CIN  64

// ---------------- device scratch (no allocation allowed) ----------------
__device__ int   g_is64;
__device__ int   g_src[EMAX];
__device__ int   g_dstE[EMAX];
__device__ int   g_esrc[EMAX];          // CSR: src ids sorted by dst
__device__ int   g_cnt[NMAX];
__device__ int   g_scan[NMAX];
__device__ int   g_bsum[512];
__device__ int   g_boff[512];
__device__ int   g_rowstart[NMAX + 1];
__device__ int   g_cur[NMAX];
__device__ float g_inv[NMAX];
__device__ __align__(256) __half g_ylh[(size_t)NMAX * 64];   // fp16 gather payload
__device__ __align__(256) float  g_yr[(size_t)NMAX * 64];
__device__ __align__(256) float  g_h0[(size_t)NMAX * 64];
__device__ __align__(256) float  g_h1[(size_t)NMAX * 64];
__device__ float g_stats[128];          // [sum(64) | sumsq(64)]
__device__ float g_aff0[128];           // [scale | shift]
__device__ float g_aff1[128];

// ---------------- packed f32x2 helpers ----------------
__device__ __forceinline__ unsigned long long pk2(float lo, float hi) {
    unsigned long long r;
    asm("mov.b64 %0, {%1, %2};" : "=l"(r) : "f"(lo), "f"(hi));
    return r;
}
__device__ __forceinline__ void upk2(unsigned long long v, float& lo, float& hi) {
    asm("mov.b64 {%0, %1}, %2;" : "=f"(lo), "=f"(hi) : "l"(v));
}
__device__ __forceinline__ void fma2(unsigned long long& d,
                                     unsigned long long a, unsigned long long b) {
    asm("fma.rn.f32x2 %0, %1, %2, %3;" : "=l"(d) : "l"(a), "l"(b), "l"(d));
}

// ---------------- dtype detection (int64 vs int32 edge_index) ----------------
__global__ void k_detect(const unsigned int* __restrict__ w) {
    int i = threadIdx.x;
    int ok = (w[2 * i + 1] == 0u) && (w[2 * (i + 1024) + 1] == 0u);
    int all = __syncthreads_and(ok);
    if (i == 0) g_is64 = all ? 1 : 0;
}

__global__ void k_zero_cnt(int N) {
    int i = blockIdx.x * blockDim.x + threadIdx.x;
    if (i < N) g_cnt[i] = 0;
}

__global__ void k_decode(const void* __restrict__ ei, int E) {
    int i = blockIdx.x * blockDim.x + threadIdx.x;
    if (i >= E) return;
    int s, d;
    if (g_is64) {
        const long long* p = (const long long*)ei;
        s = (int)p[i];
        d = (int)p[E + i];
    } else {
        const int* p = (const int*)ei;
        s = p[i];
        d = p[E + i];
    }
    g_src[i] = s;
    g_dstE[i] = d;
    atomicAdd(&g_cnt[d], 1);
}

__global__ void k_scan1(int N) {
    __shared__ int sh[256];
    int i = blockIdx.x * 256 + threadIdx.x;
    int v = (i < N) ? g_cnt[i] : 0;
    sh[threadIdx.x] = v;
    __syncthreads();
    for (int off = 1; off < 256; off <<= 1) {
        int t = (threadIdx.x >= off) ? sh[threadIdx.x - off] : 0;
        __syncthreads();
        sh[threadIdx.x] += t;
        __syncthreads();
    }
    if (i < N) g_scan[i] = sh[threadIdx.x] - v;
    if (threadIdx.x == 255) g_bsum[blockIdx.x] = sh[255];
}

__global__ void k_scan2(int NB) {
    __shared__ int sh[512];
    int i = threadIdx.x;
    int v = (i < NB) ? g_bsum[i] : 0;
    sh[i] = v;
    __syncthreads();
    for (int off = 1; off < 512; off <<= 1) {
        int t = (i >= off) ? sh[i - off] : 0;
        __syncthreads();
        sh[i] += t;
        __syncthreads();
    }
    g_boff[i] = sh[i] - v;
}

__global__ void k_scan3(int N, int E) {
    int i = blockIdx.x * blockDim.x + threadIdx.x;
    if (i < N) {
        int rs = g_scan[i] + g_boff[i >> 8];
        g_rowstart[i] = rs;
        g_cur[i] = rs;
        g_inv[i] = 1.0f / fmaxf((float)g_cnt[i], 1.0f);
    }
    if (i == N) g_rowstart[N] = E;
}

__global__ void k_fill(int E) {
    int i = blockIdx.x * blockDim.x + threadIdx.x;
    if (i >= E) return;
    int d = g_dstE[i];
    int pos = atomicAdd(&g_cur[d], 1);
    g_esrc[pos] = g_src[i];
}

// ---------------- linear: ylh = half(f(x)@Wl), yr = f(x)@Wr + b ----------------
// f = relu(aff-scale/shift) when AFFINE else identity.
// Combined weight matrix W = [Wl | Wr] of width 2*COUT staged in smem.
// 8 nodes x 1 channel-pair per thread; x vectorized float4 over k.
template <int COUT, bool AFFINE>
__global__ void __launch_bounds__((COUT / 2) * 8)
k_lin(const float* __restrict__ x,
      const float* __restrict__ aff,
      const float* __restrict__ Wl,
      const float* __restrict__ Wr,
      const float* __restrict__ bias,
      __half* __restrict__ ylh,
      float* __restrict__ yr,
      int N) {
    constexpr int W  = 2 * COUT;        // 128 or 80
    constexpr int CQ = W / 4;           // 32 or 20 channel-pair groups
    constexpr int NT = 64;              // node tile
    constexpr int THREADS = CQ * 8;     // 256 or 160
    constexpr int RS = CIN + 4;         // 68

    extern __shared__ float smem[];
    float* sX = smem;                   // NT*RS
    float* sW = sX + NT * RS;           // CIN*W

    int tid = threadIdx.x;
    // stage combined weights [k][0:COUT)=Wl row k, [COUT:W)=Wr row k
    for (int i = tid; i < CIN * W; i += THREADS) {
        int k = i / W;
        int c = i % W;
        sW[i] = (c < COUT) ? Wl[k * COUT + c] : Wr[k * COUT + (c - COUT)];
    }

    int tile = blockIdx.x * NT;
    for (int q = tid; q < NT * (CIN / 4); q += THREADS) {
        int row = q / (CIN / 4);
        int c4  = (q % (CIN / 4)) * 4;
        int n = tile + row;
        float4 xv = make_float4(0.f, 0.f, 0.f, 0.f);
        if (n < N) {
            xv = *reinterpret_cast<const float4*>(x + (size_t)n * CIN + c4);
            if (AFFINE) {
                float4 A = *reinterpret_cast<const float4*>(aff + c4);
                float4 B = *reinterpret_cast<const float4*>(aff + 64 + c4);
                xv.x = fmaxf(fmaf(xv.x, A.x, B.x), 0.f);
                xv.y = fmaxf(fmaf(xv.y, A.y, B.y), 0.f);
                xv.z = fmaxf(fmaf(xv.z, A.z, B.z), 0.f);
                xv.w = fmaxf(fmaf(xv.w, A.w, B.w), 0.f);
            }
        }
        *reinterpret_cast<float4*>(sX + row * RS + c4) = xv;
    }
    __syncthreads();

    int cg  = tid % CQ;                 // channel-pair group
    int nb  = (tid / CQ) * 8;           // node base (8 nodes per thread)
    int ch0 = 2 * cg;                   // output channel pair {ch0, ch0+1}

    unsigned long long acc0[8], acc1[8];    // Wl-product | Wr-product(+bias)
    {
        float2 b = *reinterpret_cast<const float2*>(bias + ch0);
        unsigned long long bp = pk2(b.x, b.y);
        unsigned long long zp = pk2(0.f, 0.f);
#pragma unroll
        for (int i = 0; i < 8; i++) { acc0[i] = zp; acc1[i] = bp; }
    }

    for (int k4 = 0; k4 < CIN; k4 += 4) {
        float4 xv[8];
#pragma unroll
        for (int i = 0; i < 8; i++)
            xv[i] = *reinterpret_cast<const float4*>(sX + (nb + i) * RS + k4);
#pragma unroll
        for (int kk = 0; kk < 4; kk++) {
            float2 w0 = *reinterpret_cast<const float2*>(sW + (k4 + kk) * W + ch0);
            float2 w1 = *reinterpret_cast<const float2*>(sW + (k4 + kk) * W + ch0 + COUT);
            unsigned long long w0p = pk2(w0.x, w0.y);
            unsigned long long w1p = pk2(w1.x, w1.y);
#pragma unroll
            for (int i = 0; i < 8; i++) {
                float xs = (kk == 0) ? xv[i].x : (kk == 1) ? xv[i].y
                         : (kk == 2) ? xv[i].z : xv[i].w;
                unsigned long long xp = pk2(xs, xs);
                fma2(acc0[i], xp, w0p);
                fma2(acc1[i], xp, w1p);
            }
        }
    }

#pragma unroll
    for (int i = 0; i < 8; i++) {
        int n = tile + nb + i;
        if (n < N) {
            float lo, hi;
            upk2(acc0[i], lo, hi);
            *reinterpret_cast<__half2*>(ylh + (size_t)n * COUT + ch0) =
                __floats2half2_rn(lo, hi);
            upk2(acc1[i], lo, hi);
            *reinterpret_cast<float2*>(yr + (size_t)n * COUT + ch0) =
                make_float2(lo, hi);
        }
    }
}

// ---------------- CSR gather reduce: out = invdeg * sum ylh[src] + yr ----------------
// CH = COUT/8 threads per node, each owns one 16B chunk (8 fp16 channels).
template <int COUT, bool STATS, int BLOCK>
__global__ void __launch_bounds__(BLOCK)
k_agg(const __half* __restrict__ ylh,
      const float* __restrict__ yrr,
      float* __restrict__ out,
      int N) {
    constexpr int CH = COUT / 8;

    __shared__ float sSum[64];
    __shared__ float sSq[64];
    int tid = threadIdx.x;
    if (STATS) {
        if (tid < 64) { sSum[tid] = 0.0f; sSq[tid] = 0.0f; }
        __syncthreads();
    }

    int t = blockIdx.x * BLOCK + tid;
    int n = t / CH;
    int c = (t % CH) * 8;
    bool active = (n < N);

    float r[8];
    if (active) {
        int beg = g_rowstart[n];
        int end = g_rowstart[n + 1];
        float2 a0 = make_float2(0.f, 0.f), a1 = a0, a2 = a0, a3 = a0;
#pragma unroll 2
        for (int j = beg; j < end; j++) {
            int s = __ldg(&g_esrc[j]);
            uint4 v = *reinterpret_cast<const uint4*>(ylh + (size_t)s * COUT + c);
            float2 f0 = __half22float2(*reinterpret_cast<__half2*>(&v.x));
            float2 f1 = __half22float2(*reinterpret_cast<__half2*>(&v.y));
            float2 f2 = __half22float2(*reinterpret_cast<__half2*>(&v.z));
            float2 f3 = __half22float2(*reinterpret_cast<__half2*>(&v.w));
            a0.x += f0.x; a0.y += f0.y;
            a1.x += f1.x; a1.y += f1.y;
            a2.x += f2.x; a2.y += f2.y;
            a3.x += f3.x; a3.y += f3.y;
        }
        float inv = g_inv[n];
        float4 b0 = *reinterpret_cast<const float4*>(yrr + (size_t)n * COUT + c);
        float4 b1 = *reinterpret_cast<const float4*>(yrr + (size_t)n * COUT + c + 4);
        r[0] = fmaf(a0.x, inv, b0.x);
        r[1] = fmaf(a0.y, inv, b0.y);
        r[2] = fmaf(a1.x, inv, b0.z);
        r[3] = fmaf(a1.y, inv, b0.w);
        r[4] = fmaf(a2.x, inv, b1.x);
        r[5] = fmaf(a2.y, inv, b1.y);
        r[6] = fmaf(a3.x, inv, b1.z);
        r[7] = fmaf(a3.y, inv, b1.w);
        *reinterpret_cast<float4*>(out + (size_t)n * COUT + c) =
            make_float4(r[0], r[1], r[2], r[3]);
        *reinterpret_cast<float4*>(out + (size_t)n * COUT + c + 4) =
            make_float4(r[4], r[5], r[6], r[7]);
    }

    if (STATS) {
        if (active) {
#pragma unroll
            for (int k = 0; k < 8; k++) {
                atomicAdd(&sSum[c + k], r[k]);
                atomicAdd(&sSq[c + k],  r[k] * r[k]);
            }
        }
        __syncthreads();
        if (tid < 64) {
            atomicAdd(&g_stats[tid],      sSum[tid]);
            atomicAdd(&g_stats[64 + tid], sSq[tid]);
        }
    }
}

__global__ void k_zero_stats() {
    int i = threadIdx.x;
    if (i < 128) g_stats[i] = 0.0f;
}

__global__ void k_bn_finalize(const float* __restrict__ g, const float* __restrict__ be,
                              float invN, float* __restrict__ aff) {
    int c = threadIdx.x;
    if (c < 64) {
        float mu  = g_stats[c] * invN;
        float var = g_stats[64 + c] * invN - mu * mu;
        float a = g[c] * rsqrtf(var + 1e-5f);
        aff[c] = a;
        aff[64 + c] = be[c] - mu * a;
    }
}

// ---------------- launch ----------------
extern "C" void kernel_launch(void* const* d_in, const int* in_sizes, int n_in,
                              void* d_out, int out_size) {
    const float* x   = (const float*)d_in[0];
    const void*  ei  = d_in[1];
    const float* Wl0 = (const float*)d_in[2];
    const float* Wr0 = (const float*)d_in[3];
    const float* b0  = (const float*)d_in[4];
    const float* Wl1 = (const float*)d_in[5];
    const float* Wr1 = (const float*)d_in[6];
    const float* b1  = (const float*)d_in[7];
    const float* Wl2 = (const float*)d_in[8];
    const float* Wr2 = (const float*)d_in[9];
    const float* b2  = (const float*)d_in[10];
    const float* g0  = (const float*)d_in[11];
    const float* be0 = (const float*)d_in[12];
    const float* g1  = (const float*)d_in[13];
    const float* be1 = (const float*)d_in[14];
    float* out = (float*)d_out;

    int N = in_sizes[0] / 64;
    int E = in_sizes[1] / 2;
    float invN = 1.0f / (float)N;

    __half* ylhp;
    float *yrp, *h0p, *h1p, *aff0p, *aff1p;
    cudaGetSymbolAddress((void**)&ylhp, g_ylh);
    cudaGetSymbolAddress((void**)&yrp, g_yr);
    cudaGetSymbolAddress((void**)&h0p, g_h0);
    cudaGetSymbolAddress((void**)&h1p, g_h1);
    cudaGetSymbolAddress((void**)&aff0p, g_aff0);
    cudaGetSymbolAddress((void**)&aff1p, g_aff1);

    const int smem64 = (64 * (CIN + 4) + CIN * 128) * 4;
    const int smem40 = (64 * (CIN + 4) + CIN * 80) * 4;
    cudaFuncSetAttribute(k_lin<64, false>,
                         cudaFuncAttributeMaxDynamicSharedMemorySize, smem64);
    cudaFuncSetAttribute(k_lin<64, true>,
                         cudaFuncAttributeMaxDynamicSharedMemorySize, smem64);
    cudaFuncSetAttribute(k_lin<40, true>,
                         cudaFuncAttributeMaxDynamicSharedMemorySize, smem40);

    const int nodeBlocks  = (N + 255) / 256;
    const int nodeBlocks1 = (N + 256) / 256;
    const int edgeBlocks  = (E + 255) / 256;
    const int NB          = (N + 255) / 256;
    const int agg64Blocks = (N * 8 + 255) / 256;
    const int agg40Blocks = (N * 5 + 319) / 320;
    const int mmGrid      = (N + 63) / 64;

    // ---- CSR build (round-5 structure; lin0 slotted at index 3 for ncu) ----
    k_detect<<<1, 1024>>>((const unsigned int*)ei);
    k_zero_cnt<<<nodeBlocks, 256>>>(N);
    k_decode<<<edgeBlocks, 256>>>(ei, E);
    k_lin<64, false><<<mmGrid, 256, smem64>>>(x, nullptr, Wl0, Wr0, b0, ylhp, yrp, N);
    k_scan1<<<NB, 256>>>(N);
    k_scan2<<<1, 512>>>(NB);
    k_scan3<<<nodeBlocks1, 256>>>(N, E);
    k_fill<<<edgeBlocks, 256>>>(E);

    // ---- layer 0 ----
    k_zero_stats<<<1, 128>>>();
    k_agg<64, true, 256><<<agg64Blocks, 256>>>(ylhp, yrp, h0p, N);
    k_bn_finalize<<<1, 64>>>(g0, be0, invN, aff0p);

    // ---- layer 1 ----
    k_lin<64, true><<<mmGrid, 256, smem64>>>(h0p, aff0p, Wl1, Wr1, b1, ylhp, yrp, N);
    k_zero_stats<<<1, 128>>>();
    k_agg<64, true, 256><<<agg64Blocks, 256>>>(ylhp, yrp, h1p, N);
    k_bn_finalize<<<1, 64>>>(g1, be1, invN, aff1p);

    // ---- layer 2 ----
    k_lin<40, true><<<mmGrid, 160, smem40>>>(h1p, aff1p, Wl2, Wr2, b2, ylhp, yrp, N);
    k_agg<40, false, 320><<<agg40Blocks, 320>>>(ylhp, yrp, out, N);
}